// round 1
// baseline (speedup 1.0000x reference)
#include <cuda_runtime.h>
#include <math_constants.h>

// Problem constants
#define NSL   24
#define BB    16
#define CCH   512
#define HH    16
#define WW    16
#define HWN   256          // H*W
#define FEAT_IN 1024
#define CLASSES 3

// Scratch for the concatenated feature matrix feat[B][FEAT_IN]
__device__ float g_feat[BB * FEAT_IN];

// Kernel 1: per-(b,c) reduction.
//  - task 0     : feat_f_map[b,c,:,:]   -> mean -> g_feat[b][c]
//  - tasks 1..24: oct_maps[s,b,c,:,:]   -> mean, max over s -> g_feat[b][512+c]
// Each task is 256 contiguous floats (1 KB): one warp reduces it with
// 2x float4 loads per lane + shuffle reduction. 4 warps/CTA round-robin tasks.
__global__ __launch_bounds__(128) void reduce_kernel(
    const float* __restrict__ feat_f_map,
    const float* __restrict__ oct_maps)
{
    const int bc   = blockIdx.x;          // 0 .. B*C-1
    const int b    = bc >> 9;             // /512
    const int c    = bc & (CCH - 1);      // %512
    const int warp = threadIdx.x >> 5;
    const int lane = threadIdx.x & 31;

    __shared__ float s_max[4];
    __shared__ float s_ff;

    const float* ff_base = feat_f_map + (size_t)bc * HWN;

    float local_max = -CUDART_INF_F;

    #pragma unroll
    for (int t = warp; t < NSL + 1; t += 4) {
        const float* base = (t == 0)
            ? ff_base
            : oct_maps + (((size_t)(t - 1) * BB + b) * CCH + c) * HWN;
        const float4* p = (const float4*)base;
        float4 v0 = p[lane];        // floats [4*lane .. 4*lane+3]
        float4 v1 = p[lane + 32];   // floats [128+4*lane ..]
        float s = (v0.x + v0.y) + (v0.z + v0.w)
                + (v1.x + v1.y) + (v1.z + v1.w);
        #pragma unroll
        for (int off = 16; off; off >>= 1)
            s += __shfl_xor_sync(0xffffffffu, s, off);
        if (t == 0) {
            if (lane == 0) s_ff = s;
        } else {
            local_max = fmaxf(local_max, s);
        }
    }
    if (lane == 0) s_max[warp] = local_max;
    __syncthreads();

    if (threadIdx.x == 0) {
        float m = fmaxf(fmaxf(s_max[0], s_max[1]), fmaxf(s_max[2], s_max[3]));
        const float inv = 1.0f / (float)HWN;
        g_feat[b * FEAT_IN + c]        = s_ff * inv;   // feat_f
        g_feat[b * FEAT_IN + CCH + c]  = m    * inv;   // feat_o = max of means
    }
}

// Kernel 2: labels[b][cl] = feat[b] . head_w[cl] + head_b[cl]
// 48 outputs, one CTA each, 256-thread strided dot + block reduce. Trivial cost.
__global__ __launch_bounds__(256) void head_kernel(
    const float* __restrict__ head_w,
    const float* __restrict__ head_b,
    float* __restrict__ out)
{
    const int o  = blockIdx.x;            // 0 .. 47
    const int b  = o / CLASSES;
    const int cl = o % CLASSES;

    float s = 0.f;
    const float* f = &g_feat[b * FEAT_IN];
    const float* w = &head_w[cl * FEAT_IN];
    for (int k = threadIdx.x; k < FEAT_IN; k += 256)
        s += f[k] * w[k];

    #pragma unroll
    for (int off = 16; off; off >>= 1)
        s += __shfl_xor_sync(0xffffffffu, s, off);

    __shared__ float sh[8];
    const int warp = threadIdx.x >> 5;
    const int lane = threadIdx.x & 31;
    if (lane == 0) sh[warp] = s;
    __syncthreads();

    if (threadIdx.x == 0) {
        float t = 0.f;
        #pragma unroll
        for (int w8 = 0; w8 < 8; w8++) t += sh[w8];
        out[o] = t + head_b[cl];
    }
}

extern "C" void kernel_launch(void* const* d_in, const int* in_sizes, int n_in,
                              void* d_out, int out_size)
{
    const float* feat_f_map = (const float*)d_in[0];  // (16,512,16,16)
    const float* oct_maps   = (const float*)d_in[1];  // (24,16,512,16,16)
    const float* head_w     = (const float*)d_in[2];  // (3,1024)
    const float* head_b     = (const float*)d_in[3];  // (3,)
    float* out = (float*)d_out;                        // (16,3)

    reduce_kernel<<<BB * CCH, 128>>>(feat_f_map, oct_maps);
    head_kernel<<<BB * CLASSES, 256>>>(head_w, head_b, out);
}